// round 7
// baseline (speedup 1.0000x reference)
#include <cuda_runtime.h>
#include <cuda_bf16.h>
#include <math.h>
#include <cstdint>

#define N_TOK 65536
#define DIM 256
#define CB 2048
#define DECAY 0.99f
#define ONE_MINUS 0.01f
#define EPS 1e-5f

// output layout (float32 elements, reference return order)
#define OUT_Q    0u
#define OUT_IDX  16777216u
#define OUT_EMB  16842752u
#define OUT_CS   17367040u
#define OUT_EAVG 17369088u

#define TAU  0.02f      // bf16-pass flag threshold (~9 sigma of bf16 margin error)
#define TAU2 1e-3f      // fp32-pass flag threshold (~60 sigma of fp32 error)
#define MAXFLAG  32768
#define MAXFLAG2 8192

// ---------------- scratch (device globals; no allocations) ----------------
__device__ float g_cn[CB * DIM];                               // normalized codebook fp32
__device__ __align__(128) unsigned char g_cnb[CB * DIM * 2];   // bf16, tile-swizzled
__device__ float g_counts[CB];
__device__ float g_embed_sum[CB * DIM];
__device__ float g_cs_smooth[CB];
__device__ int   g_idx[N_TOK];
__device__ int   g_flag_rows[MAXFLAG];
__device__ int   g_flag_count;
__device__ int   g_flag2_rows[MAXFLAG2];
__device__ int   g_flag2_count;

// ================= PTX helpers =============================================
__device__ __forceinline__ uint32_t smem_u32(const void* p) {
    uint32_t a;
    asm("{ .reg .u64 t; cvta.to.shared.u64 t, %1; cvt.u32.u64 %0, t; }" : "=r"(a) : "l"(p));
    return a;
}

#define CP_ASYNC16(dst, src) \
    asm volatile("cp.async.cg.shared.global [%0], [%1], 16;" :: "r"(dst), "l"(src) : "memory")
#define CP_COMMIT() asm volatile("cp.async.commit_group;" ::: "memory")
#define CP_WAIT1()  asm volatile("cp.async.wait_group 1;" ::: "memory")

#define LDSM_X4(r0, r1, r2, r3, addr) \
    asm volatile("ldmatrix.sync.aligned.m8n8.x4.shared.b16 {%0,%1,%2,%3}, [%4];" \
        : "=r"(r0), "=r"(r1), "=r"(r2), "=r"(r3) : "r"(addr))

#define MMA16816(d, a0, a1, a2, a3, b0, b1) \
    asm volatile("mma.sync.aligned.m16n8k16.row.col.f32.bf16.bf16.f32 " \
        "{%0,%1,%2,%3}, {%4,%5,%6,%7}, {%8,%9}, {%0,%1,%2,%3};" \
        : "+f"((d)[0]), "+f"((d)[1]), "+f"((d)[2]), "+f"((d)[3]) \
        : "r"(a0), "r"(a1), "r"(a2), "r"(a3), "r"(b0), "r"(b1))

// ---------------- kernel 1: normalize codes + bf16 + zero accum ------------
__global__ void k_setup(const float* __restrict__ embed) {
    int c = blockIdx.x, t = threadIdx.x;
    float v = embed[c * DIM + t];
    float s = v * v;
    #pragma unroll
    for (int o = 16; o; o >>= 1) s += __shfl_xor_sync(0xffffffffu, s, o);
    __shared__ float red[8];
    if ((t & 31) == 0) red[t >> 5] = s;
    __syncthreads();
    if (t < 32) {
        float q = (t < 8) ? red[t] : 0.f;
        #pragma unroll
        for (int o = 4; o; o >>= 1) q += __shfl_xor_sync(0xffffffffu, q, o);
        if (t == 0) red[0] = q;
    }
    __syncthreads();
    float n = fmaxf(sqrtf(red[0]), 1e-12f);
    float cn = v / n;
    g_cn[c * DIM + t] = cn;

    // bf16 into 32-code tile layout with XOR16 swizzle
    int tile = c >> 5;
    int r = c & 31;
    int k = t;
    uint32_t off = (uint32_t)tile * 16384u + (uint32_t)r * 512u
                 + (uint32_t)((((k >> 3) ^ (r & 7)) << 4) + (k & 7) * 2);
    *(__nv_bfloat16*)(g_cnb + off) = __float2bfloat16(cn);

    g_embed_sum[c * DIM + t] = 0.f;
    if (t == 0) {
        g_counts[c] = 0.f;
        if (c == 0) { g_flag_count = 0; g_flag2_count = 0; }
    }
}

// ---------------- kernel 2: bf16 HMMA GEMM + fused per-row top-2 -----------
// 256 threads = 8 warps; warp w owns rows [w*16, w*16+16).
// smem: A [0,64K), B double buffer [64K,96K). 96KB -> 2 CTAs/SM.
__global__ void __launch_bounds__(256, 2)
k_mma(const float* __restrict__ x) {
    extern __shared__ __align__(128) unsigned char sm[];
    uint32_t sb = smem_u32(sm);
    int tid = threadIdx.x;
    int warp = tid >> 5, lane = tid & 31;
    int rowBase = blockIdx.x * 128;

    // ---- prefetch first two B tiles ----
    {
        const unsigned char* sH = g_cnb;
        uint32_t d0 = sb + 65536u;
        #pragma unroll
        for (int i = 0; i < 4; i++) {
            uint32_t id = (uint32_t)(tid + i * 256) * 16u;
            CP_ASYNC16(d0 + id, sH + id);
        }
        CP_COMMIT();
        uint32_t d1 = sb + 65536u + 16384u;
        #pragma unroll
        for (int i = 0; i < 4; i++) {
            uint32_t id = (uint32_t)(tid + i * 256) * 16u;
            CP_ASYNC16(d1 + id, sH + 16384u + id);
        }
        CP_COMMIT();
    }

    // ---- stage A: x -> bf16 swizzled smem ----
    {
        const float4* x4 = (const float4*)x + (size_t)rowBase * 64;
        #pragma unroll
        for (int i = 0; i < 32; i++) {
            int p = tid + i * 256;          // 0..8191
            int r = p >> 6, kq = p & 63;
            int k = kq * 4;
            float4 v = x4[(size_t)r * 64 + kq];
            __nv_bfloat162 h0 = __floats2bfloat162_rn(v.x, v.y);
            __nv_bfloat162 h1 = __floats2bfloat162_rn(v.z, v.w);
            uint32_t off = (uint32_t)r * 512u
                         + (uint32_t)((((k >> 3) ^ (r & 7)) << 4) + (k & 7) * 2);
            *(uint32_t*)(sm + off)     = *(uint32_t*)&h0;
            *(uint32_t*)(sm + off + 4) = *(uint32_t*)&h1;
        }
    }
    __syncthreads();

    // ---- per-lane ldmatrix address components ----
    int q = lane >> 3, ja = lane & 7;
    int arow = warp * 16 + ((q & 1) << 3) + ja;
    uint32_t aRowOff = (uint32_t)arow * 512u;
    int aSw = arow & 7;
    int aKadd = q >> 1;
    int browL = ((q >> 1) << 3) + ja;
    int bKadd = q & 1;
    uint32_t bOffL0 = (uint32_t)browL * 512u;
    uint32_t bOffL1 = (uint32_t)(16 + browL) * 512u;
    int bSw0 = browL & 7;
    int bSw1 = (16 + browL) & 7;

    float best0 = -1e30f, sec0 = -1e30f, best1 = -1e30f, sec1 = -1e30f;
    int idx0 = 0, idx1 = 0;

    for (int t = 0; t < 64; t++) {
        CP_WAIT1();
        __syncthreads();

        uint32_t bB = sb + 65536u + (uint32_t)(t & 1) * 16384u;

        float C[4][4];
        #pragma unroll
        for (int nt = 0; nt < 4; nt++)
            #pragma unroll
            for (int j = 0; j < 4; j++) C[nt][j] = 0.f;

        #pragma unroll
        for (int ks = 0; ks < 16; ks++) {
            int c0 = ks * 2;
            uint32_t aOff = aRowOff + (uint32_t)(((c0 + aKadd) ^ aSw) << 4);
            uint32_t a0, a1, a2, a3;
            LDSM_X4(a0, a1, a2, a3, sb + aOff);

            uint32_t bO0 = bOffL0 + (uint32_t)(((c0 + bKadd) ^ bSw0) << 4);
            uint32_t bO1 = bOffL1 + (uint32_t)(((c0 + bKadd) ^ bSw1) << 4);

            uint32_t b0, b1, b2, b3;
            LDSM_X4(b0, b1, b2, b3, bB + bO0);
            MMA16816(C[0], a0, a1, a2, a3, b0, b1);
            MMA16816(C[1], a0, a1, a2, a3, b2, b3);

            LDSM_X4(b0, b1, b2, b3, bB + bO1);
            MMA16816(C[2], a0, a1, a2, a3, b0, b1);
            MMA16816(C[3], a0, a1, a2, a3, b2, b3);
        }

        #pragma unroll
        for (int nt = 0; nt < 4; nt++) {
            int col = t * 32 + nt * 8 + 2 * (lane & 3);
            float v;
            v = C[nt][0];
            if (v > best0) { sec0 = best0; best0 = v; idx0 = col; }
            else if (v > sec0) sec0 = v;
            v = C[nt][1];
            if (v > best0) { sec0 = best0; best0 = v; idx0 = col + 1; }
            else if (v > sec0) sec0 = v;
            v = C[nt][2];
            if (v > best1) { sec1 = best1; best1 = v; idx1 = col; }
            else if (v > sec1) sec1 = v;
            v = C[nt][3];
            if (v > best1) { sec1 = best1; best1 = v; idx1 = col + 1; }
            else if (v > sec1) sec1 = v;
        }

        __syncthreads();
        if (t + 2 < 64) {
            const unsigned char* sH = g_cnb + (size_t)(t + 2) * 16384;
            uint32_t d = sb + 65536u + (uint32_t)(t & 1) * 16384u;
            #pragma unroll
            for (int i = 0; i < 4; i++) {
                uint32_t id = (uint32_t)(tid + i * 256) * 16u;
                CP_ASYNC16(d + id, sH + id);
            }
        }
        CP_COMMIT();
    }

    // ---- reduce top-2 across the quad ----
    #pragma unroll
    for (int off = 1; off <= 2; off <<= 1) {
        float ob = __shfl_xor_sync(0xffffffffu, best0, off);
        float os = __shfl_xor_sync(0xffffffffu, sec0, off);
        int   oi = __shfl_xor_sync(0xffffffffu, idx0, off);
        if (ob > best0 || (ob == best0 && oi < idx0)) {
            sec0 = fmaxf(best0, os); best0 = ob; idx0 = oi;
        } else sec0 = fmaxf(sec0, ob);
        ob = __shfl_xor_sync(0xffffffffu, best1, off);
        os = __shfl_xor_sync(0xffffffffu, sec1, off);
        oi = __shfl_xor_sync(0xffffffffu, idx1, off);
        if (ob > best1 || (ob == best1 && oi < idx1)) {
            sec1 = fmaxf(best1, os); best1 = ob; idx1 = oi;
        } else sec1 = fmaxf(sec1, ob);
    }

    if ((lane & 3) == 0) {
        int r0 = rowBase + warp * 16 + (lane >> 2);
        int r1 = r0 + 8;
        g_idx[r0] = idx0;
        g_idx[r1] = idx1;
        if (best0 - sec0 < TAU) {
            int p = atomicAdd(&g_flag_count, 1);
            if (p < MAXFLAG) g_flag_rows[p] = r0;
        }
        if (best1 - sec1 < TAU) {
            int p = atomicAdd(&g_flag_count, 1);
            if (p < MAXFLAG) g_flag_rows[p] = r1;
        }
    }
}

// ---------------- kernel 3: fp32 SIMT refine GEMM over flagged rows --------
// 256 threads (tx=tid&15 -> 4 cols, ty=tid>>4 -> 8 rows); BM=128, BC=64.
__global__ void __launch_bounds__(256, 1)
k_refine32(const float* __restrict__ x) {
    extern __shared__ float smf[];
    float* xsT = smf;                  // [DIM][128]
    float* csT = smf + DIM * 128;      // [DIM][64]
    int nf = g_flag_count;
    if (nf > MAXFLAG) nf = MAXFLAG;
    int base = blockIdx.x * 128;
    if (base >= nf) return;

    int tid = threadIdx.x;
    int tx = tid & 15, ty = tid >> 4;

    const float4* x4 = (const float4*)x;
    for (int p = tid; p < 128 * 64; p += 256) {
        int r = p >> 6, kq = p & 63;
        int fr = base + r;
        int row = g_flag_rows[fr < nf ? fr : (nf - 1)];
        float4 g = x4[(size_t)row * 64 + kq];
        int k = kq * 4;
        xsT[(k + 0) * 128 + r] = g.x;
        xsT[(k + 1) * 128 + r] = g.y;
        xsT[(k + 2) * 128 + r] = g.z;
        xsT[(k + 3) * 128 + r] = g.w;
    }

    float best[8], sec[8];
    int bidx[8];
    #pragma unroll
    for (int i = 0; i < 8; i++) { best[i] = -1e30f; sec[i] = -1e30f; bidx[i] = 0; }

    const float4* cn4 = (const float4*)g_cn;
    for (int c0 = 0; c0 < CB; c0 += 64) {
        __syncthreads();
        for (int p = tid; p < 64 * 64; p += 256) {
            int r = p >> 6, kq = p & 63;
            float4 g = cn4[(size_t)(c0 + r) * 64 + kq];
            int k = kq * 4;
            csT[(k + 0) * 64 + r] = g.x;
            csT[(k + 1) * 64 + r] = g.y;
            csT[(k + 2) * 64 + r] = g.z;
            csT[(k + 3) * 64 + r] = g.w;
        }
        __syncthreads();

        float acc[8][4];
        #pragma unroll
        for (int i = 0; i < 8; i++)
            #pragma unroll
            for (int j = 0; j < 4; j++) acc[i][j] = 0.f;

        #pragma unroll 4
        for (int k = 0; k < DIM; k++) {
            float4 xa = *(const float4*)&xsT[k * 128 + ty * 8];
            float4 xb = *(const float4*)&xsT[k * 128 + ty * 8 + 4];
            float4 cv = *(const float4*)&csT[k * 64 + tx * 4];
            float xr[8] = {xa.x, xa.y, xa.z, xa.w, xb.x, xb.y, xb.z, xb.w};
            float cc[4] = {cv.x, cv.y, cv.z, cv.w};
            #pragma unroll
            for (int i = 0; i < 8; i++)
                #pragma unroll
                for (int j = 0; j < 4; j++)
                    acc[i][j] = fmaf(xr[i], cc[j], acc[i][j]);
        }

        #pragma unroll
        for (int i = 0; i < 8; i++) {
            #pragma unroll
            for (int j = 0; j < 4; j++) {
                float v = acc[i][j];
                int c = c0 + tx * 4 + j;
                if (v > best[i]) { sec[i] = best[i]; best[i] = v; bidx[i] = c; }
                else if (v > sec[i]) sec[i] = v;
            }
        }
    }

    #pragma unroll
    for (int i = 0; i < 8; i++) {
        #pragma unroll
        for (int off = 8; off; off >>= 1) {
            float ob = __shfl_xor_sync(0xffffffffu, best[i], off);
            float os = __shfl_xor_sync(0xffffffffu, sec[i], off);
            int   oi = __shfl_xor_sync(0xffffffffu, bidx[i], off);
            if (ob > best[i] || (ob == best[i] && oi < bidx[i])) {
                sec[i] = fmaxf(best[i], os);
                best[i] = ob; bidx[i] = oi;
            } else {
                sec[i] = fmaxf(sec[i], ob);
            }
        }
    }

    if (tx == 0) {
        #pragma unroll
        for (int i = 0; i < 8; i++) {
            int fr = base + ty * 8 + i;
            if (fr < nf) {
                int row = g_flag_rows[fr];
                g_idx[row] = bidx[i];
                if (best[i] - sec[i] < TAU2) {
                    int p = atomicAdd(&g_flag2_count, 1);
                    if (p < MAXFLAG2) g_flag2_rows[p] = row;
                }
            }
        }
    }
}

// ---------------- kernel 4: fp64 refine for true near-ties -----------------
__global__ void k_refine64(const float* __restrict__ x) {
    __shared__ float xs[DIM];
    __shared__ double sv[256];
    __shared__ int si[256];
    int t = threadIdx.x;
    int nf = g_flag2_count;
    if (nf > MAXFLAG2) nf = MAXFLAG2;
    for (int f = blockIdx.x; f < nf; f += gridDim.x) {
        int row = g_flag2_rows[f];
        xs[t] = x[(size_t)row * DIM + t];
        __syncthreads();
        double bb = -1e300; int bi = 0;
        for (int c = t; c < CB; c += 256) {
            const float* cr = g_cn + (size_t)c * DIM;
            double s = 0.0;
            #pragma unroll 8
            for (int d = 0; d < DIM; d++) s += (double)xs[d] * (double)cr[d];
            if (s > bb) { bb = s; bi = c; }
        }
        sv[t] = bb; si[t] = bi;
        __syncthreads();
        for (int srt = 128; srt; srt >>= 1) {
            if (t < srt) {
                if (sv[t + srt] > sv[t] ||
                    (sv[t + srt] == sv[t] && si[t + srt] < si[t])) {
                    sv[t] = sv[t + srt]; si[t] = si[t + srt];
                }
            }
            __syncthreads();
        }
        if (t == 0) g_idx[row] = si[0];
        __syncthreads();
    }
}

// ---------------- kernel 5: gather quantized + scatter sums ----------------
__global__ void k_assign(const float* __restrict__ x,
                         const float* __restrict__ embed,
                         float* __restrict__ out) {
    int warp = threadIdx.x >> 5, lane = threadIdx.x & 31;
    int row = blockIdx.x * 8 + warp;
    int idx = g_idx[row];
    const float4* e4 = (const float4*)(embed + (size_t)idx * DIM);
    const float4* xv4 = (const float4*)(x + (size_t)row * DIM);
    float4* q4 = (float4*)(out + OUT_Q + (size_t)row * DIM);
    float* es = g_embed_sum + (size_t)idx * DIM;
    #pragma unroll
    for (int h = 0; h < 2; h++) {
        int d4 = lane + h * 32;
        q4[d4] = e4[d4];
        float4 xv = xv4[d4];
        atomicAdd(es + d4 * 4 + 0, xv.x);
        atomicAdd(es + d4 * 4 + 1, xv.y);
        atomicAdd(es + d4 * 4 + 2, xv.z);
        atomicAdd(es + d4 * 4 + 3, xv.w);
    }
    if (lane == 0) {
        atomicAdd(&g_counts[idx], 1.0f);
        out[OUT_IDX + row] = (float)idx;
    }
}

// ---------------- kernel 6: EMA cluster size + laplace smoothing -----------
__global__ void k_cs(const float* __restrict__ cluster_size,
                     float* __restrict__ out) {
    int t = threadIdx.x;  // 1024 threads
    __shared__ float red[32];
    __shared__ float s_tot;
    float local = 0.f;
    float ncs[2];
    #pragma unroll
    for (int h = 0; h < 2; h++) {
        int c = t + h * 1024;
        ncs[h] = cluster_size[c] * DECAY + g_counts[c] * ONE_MINUS;
        out[OUT_CS + c] = ncs[h];
        local += ncs[h];
    }
    #pragma unroll
    for (int o = 16; o; o >>= 1) local += __shfl_xor_sync(0xffffffffu, local, o);
    if ((t & 31) == 0) red[t >> 5] = local;
    __syncthreads();
    if (t < 32) {
        float q = red[t];
        #pragma unroll
        for (int o = 16; o; o >>= 1) q += __shfl_xor_sync(0xffffffffu, q, o);
        if (t == 0) s_tot = q;
    }
    __syncthreads();
    float total = s_tot;
    float denom = total + CB * EPS;
    #pragma unroll
    for (int h = 0; h < 2; h++) {
        int c = t + h * 1024;
        g_cs_smooth[c] = (ncs[h] + EPS) / denom * total;
    }
}

// ---------------- kernel 7: EMA embed_avg + row normalize ------------------
__global__ void k_embed(const float* __restrict__ embed_avg,
                        float* __restrict__ out) {
    int c = blockIdx.x, t = threadIdx.x;
    float ea = embed_avg[c * DIM + t] * DECAY + g_embed_sum[c * DIM + t] * ONE_MINUS;
    out[OUT_EAVG + c * DIM + t] = ea;
    float v = ea / g_cs_smooth[c];
    float s = v * v;
    #pragma unroll
    for (int o = 16; o; o >>= 1) s += __shfl_xor_sync(0xffffffffu, s, o);
    __shared__ float red[8];
    if ((t & 31) == 0) red[t >> 5] = s;
    __syncthreads();
    if (t < 32) {
        float q = (t < 8) ? red[t] : 0.f;
        #pragma unroll
        for (int o = 4; o; o >>= 1) q += __shfl_xor_sync(0xffffffffu, q, o);
        if (t == 0) red[0] = q;
    }
    __syncthreads();
    float n = fmaxf(sqrtf(red[0]), 1e-12f);
    out[OUT_EMB + c * DIM + t] = v / n;
}

// ---------------- launch ---------------------------------------------------
extern "C" void kernel_launch(void* const* d_in, const int* in_sizes, int n_in,
                              void* d_out, int out_size) {
    const float* x            = (const float*)d_in[0];
    const float* embed        = (const float*)d_in[1];
    const float* cluster_size = (const float*)d_in[2];
    const float* embed_avg    = (const float*)d_in[3];
    float* out = (float*)d_out;

    (void)in_sizes; (void)n_in; (void)out_size;

    const int MMA_SMEM = 98304;   // 64KB A + 2x16KB B
    const int R32_SMEM = 196608;  // 128KB xT + 64KB cT
    cudaFuncSetAttribute(k_mma, cudaFuncAttributeMaxDynamicSharedMemorySize, MMA_SMEM);
    cudaFuncSetAttribute(k_refine32, cudaFuncAttributeMaxDynamicSharedMemorySize, R32_SMEM);

    k_setup<<<CB, DIM>>>(embed);
    k_mma<<<N_TOK / 128, 256, MMA_SMEM>>>(x);
    k_refine32<<<MAXFLAG / 128, 256, R32_SMEM>>>(x);
    k_refine64<<<148, 256>>>(x);
    k_assign<<<N_TOK / 8, 256>>>(x, embed, out);
    k_cs<<<1, 1024>>>(cluster_size, out);
    k_embed<<<CB, DIM>>>(embed_avg, out);
}

// round 8
// speedup vs baseline: 1.1439x; 1.1439x over previous
#include <cuda_runtime.h>
#include <cuda_bf16.h>
#include <math.h>
#include <cstdint>

#define N_TOK 65536
#define DIM 256
#define CB 2048
#define DECAY 0.99f
#define ONE_MINUS 0.01f
#define EPS 1e-5f

// output layout (float32 elements, reference return order)
#define OUT_Q    0u
#define OUT_IDX  16777216u
#define OUT_EMB  16842752u
#define OUT_CS   17367040u
#define OUT_EAVG 17369088u

#define TAU 1e-3f
#define MAXFLAG 16384

// ---------------- scratch (device globals; no allocations) ----------------
__device__ float g_cn[CB * DIM];                               // normalized codebook fp32 (refine)
__device__ __align__(128) unsigned char g_cnb_hi[CB * DIM * 2];// bf16 hi, tile-swizzled
__device__ __align__(128) unsigned char g_cnb_lo[CB * DIM * 2];// bf16 lo, tile-swizzled
__device__ float g_counts[CB];
__device__ float g_embed_sum[CB * DIM];
__device__ float g_cs_smooth[CB];
__device__ int   g_idx[N_TOK];
__device__ int   g_flag_rows[MAXFLAG];
__device__ int   g_flag_count;

// ================= PTX helpers =============================================
__device__ __forceinline__ uint32_t smem_u32(const void* p) {
    uint32_t a;
    asm("{ .reg .u64 t; cvta.to.shared.u64 t, %1; cvt.u32.u64 %0, t; }" : "=r"(a) : "l"(p));
    return a;
}

#define CP_ASYNC16(dst, src) \
    asm volatile("cp.async.cg.shared.global [%0], [%1], 16;" :: "r"(dst), "l"(src) : "memory")
#define CP_COMMIT() asm volatile("cp.async.commit_group;" ::: "memory")
#define CP_WAIT1()  asm volatile("cp.async.wait_group 1;" ::: "memory")

#define LDSM_X4(r0, r1, r2, r3, addr) \
    asm volatile("ldmatrix.sync.aligned.m8n8.x4.shared.b16 {%0,%1,%2,%3}, [%4];" \
        : "=r"(r0), "=r"(r1), "=r"(r2), "=r"(r3) : "r"(addr))

#define MMA16816(d, a0, a1, a2, a3, b0, b1) \
    asm volatile("mma.sync.aligned.m16n8k16.row.col.f32.bf16.bf16.f32 " \
        "{%0,%1,%2,%3}, {%4,%5,%6,%7}, {%8,%9}, {%0,%1,%2,%3};" \
        : "+f"((d)[0]), "+f"((d)[1]), "+f"((d)[2]), "+f"((d)[3]) \
        : "r"(a0), "r"(a1), "r"(a2), "r"(a3), "r"(b0), "r"(b1))

// ---------------- kernel 1: normalize codes + bf16 hi/lo + zero accum -----
__global__ void k_setup(const float* __restrict__ embed) {
    int c = blockIdx.x, t = threadIdx.x;
    float v = embed[c * DIM + t];
    float s = v * v;
    #pragma unroll
    for (int o = 16; o; o >>= 1) s += __shfl_xor_sync(0xffffffffu, s, o);
    __shared__ float red[8];
    if ((t & 31) == 0) red[t >> 5] = s;
    __syncthreads();
    if (t < 32) {
        float q = (t < 8) ? red[t] : 0.f;
        #pragma unroll
        for (int o = 4; o; o >>= 1) q += __shfl_xor_sync(0xffffffffu, q, o);
        if (t == 0) red[0] = q;
    }
    __syncthreads();
    float n = fmaxf(sqrtf(red[0]), 1e-12f);
    float cn = v / n;
    g_cn[c * DIM + t] = cn;

    // bf16 hi/lo into 32-code tile layout with XOR16 swizzle
    __nv_bfloat16 hb = __float2bfloat16(cn);
    float hf = __bfloat162float(hb);
    __nv_bfloat16 lb = __float2bfloat16(cn - hf);
    int tile = c >> 5;
    int r = c & 31;
    int k = t;
    uint32_t off = (uint32_t)tile * 16384u + (uint32_t)r * 512u
                 + (uint32_t)((((k >> 3) ^ (r & 7)) << 4) + (k & 7) * 2);
    *(__nv_bfloat16*)(g_cnb_hi + off) = hb;
    *(__nv_bfloat16*)(g_cnb_lo + off) = lb;

    g_embed_sum[c * DIM + t] = 0.f;
    if (t == 0) {
        g_counts[c] = 0.f;
        if (c == 0) g_flag_count = 0;
    }
}

// ---------------- kernel 2: bf16x3 HMMA GEMM + fused per-row top-2 ---------
// 256 threads = 8 warps; warp w owns rows [w*16, w*16+16).
// smem: A_hi [0,64K), A_lo [64K,128K), B double buffer [128K,192K)
//       (buf = 32KB: hi 16KB + lo 16KB), each a 32-code tile of K=256.
__global__ void __launch_bounds__(256, 1)
k_mma(const float* __restrict__ x) {
    extern __shared__ __align__(128) unsigned char sm[];
    uint32_t sb = smem_u32(sm);
    int tid = threadIdx.x;
    int warp = tid >> 5, lane = tid & 31;
    int rowBase = blockIdx.x * 128;

    // ---- prefetch first two B tiles ----
    {
        const unsigned char* sH = g_cnb_hi;
        const unsigned char* sL = g_cnb_lo;
        uint32_t d0 = sb + 131072u;
        #pragma unroll
        for (int i = 0; i < 4; i++) {
            uint32_t id = (uint32_t)(tid + i * 256) * 16u;
            CP_ASYNC16(d0 + id, sH + id);
            CP_ASYNC16(d0 + 16384u + id, sL + id);
        }
        CP_COMMIT();
        uint32_t d1 = sb + 131072u + 32768u;
        #pragma unroll
        for (int i = 0; i < 4; i++) {
            uint32_t id = (uint32_t)(tid + i * 256) * 16u;
            CP_ASYNC16(d1 + id, sH + 16384u + id);
            CP_ASYNC16(d1 + 16384u + id, sL + 16384u + id);
        }
        CP_COMMIT();
    }

    // ---- stage A: x -> bf16 hi/lo swizzled smem ----
    {
        const float4* x4 = (const float4*)x + (size_t)rowBase * 64;
        #pragma unroll
        for (int i = 0; i < 32; i++) {
            int p = tid + i * 256;          // 0..8191
            int r = p >> 6, kq = p & 63;
            int k = kq * 4;
            float4 v = x4[(size_t)r * 64 + kq];
            __nv_bfloat162 h0 = __floats2bfloat162_rn(v.x, v.y);
            __nv_bfloat162 h1 = __floats2bfloat162_rn(v.z, v.w);
            float2 f0 = __bfloat1622float2(h0);
            float2 f1 = __bfloat1622float2(h1);
            __nv_bfloat162 l0 = __floats2bfloat162_rn(v.x - f0.x, v.y - f0.y);
            __nv_bfloat162 l1 = __floats2bfloat162_rn(v.z - f1.x, v.w - f1.y);
            uint32_t off = (uint32_t)r * 512u
                         + (uint32_t)((((k >> 3) ^ (r & 7)) << 4) + (k & 7) * 2);
            *(uint32_t*)(sm + off)           = *(uint32_t*)&h0;
            *(uint32_t*)(sm + off + 4)       = *(uint32_t*)&h1;
            *(uint32_t*)(sm + 65536u + off)     = *(uint32_t*)&l0;
            *(uint32_t*)(sm + 65536u + off + 4) = *(uint32_t*)&l1;
        }
    }
    __syncthreads();

    // ---- per-lane ldmatrix address components ----
    int q = lane >> 3, ja = lane & 7;
    int arow = warp * 16 + ((q & 1) << 3) + ja;  // A matrices: q&1 -> +8 rows, q>>1 -> +8 k
    uint32_t aRowOff = (uint32_t)arow * 512u;
    int aSw = arow & 7;
    int aKadd = q >> 1;
    int browL = ((q >> 1) << 3) + ja;            // B matrices: q>>1 -> +8 rows, q&1 -> +8 k
    int bKadd = q & 1;
    uint32_t bOffL0 = (uint32_t)browL * 512u;          // rows 0..15 block
    uint32_t bOffL1 = (uint32_t)(16 + browL) * 512u;   // rows 16..31 block
    int bSw0 = browL & 7;
    int bSw1 = (16 + browL) & 7;

    float best0 = -1e30f, sec0 = -1e30f, best1 = -1e30f, sec1 = -1e30f;
    int idx0 = 0, idx1 = 0;

    for (int t = 0; t < 64; t++) {
        CP_WAIT1();
        __syncthreads();

        uint32_t bHiB = sb + 131072u + (uint32_t)(t & 1) * 32768u;
        uint32_t bLoB = bHiB + 16384u;

        float C[4][4];
        #pragma unroll
        for (int nt = 0; nt < 4; nt++)
            #pragma unroll
            for (int j = 0; j < 4; j++) C[nt][j] = 0.f;

        #pragma unroll
        for (int ks = 0; ks < 16; ks++) {
            int c0 = ks * 2;
            uint32_t aOff = aRowOff + (uint32_t)(((c0 + aKadd) ^ aSw) << 4);
            uint32_t ah0, ah1, ah2, ah3, al0, al1, al2, al3;
            LDSM_X4(ah0, ah1, ah2, ah3, sb + aOff);
            LDSM_X4(al0, al1, al2, al3, sb + 65536u + aOff);

            uint32_t bO0 = bOffL0 + (uint32_t)(((c0 + bKadd) ^ bSw0) << 4);
            uint32_t bO1 = bOffL1 + (uint32_t)(((c0 + bKadd) ^ bSw1) << 4);

            uint32_t bh0, bh1, bh2, bh3, bl0, bl1, bl2, bl3;
            LDSM_X4(bh0, bh1, bh2, bh3, bHiB + bO0);
            LDSM_X4(bl0, bl1, bl2, bl3, bLoB + bO0);
            MMA16816(C[0], ah0, ah1, ah2, ah3, bh0, bh1);
            MMA16816(C[1], ah0, ah1, ah2, ah3, bh2, bh3);
            MMA16816(C[0], al0, al1, al2, al3, bh0, bh1);
            MMA16816(C[1], al0, al1, al2, al3, bh2, bh3);
            MMA16816(C[0], ah0, ah1, ah2, ah3, bl0, bl1);
            MMA16816(C[1], ah0, ah1, ah2, ah3, bl2, bl3);

            LDSM_X4(bh0, bh1, bh2, bh3, bHiB + bO1);
            LDSM_X4(bl0, bl1, bl2, bl3, bLoB + bO1);
            MMA16816(C[2], ah0, ah1, ah2, ah3, bh0, bh1);
            MMA16816(C[3], ah0, ah1, ah2, ah3, bh2, bh3);
            MMA16816(C[2], al0, al1, al2, al3, bh0, bh1);
            MMA16816(C[3], al0, al1, al2, al3, bh2, bh3);
            MMA16816(C[2], ah0, ah1, ah2, ah3, bl0, bl1);
            MMA16816(C[3], ah0, ah1, ah2, ah3, bl2, bl3);
        }

        // fold C into per-lane top-2 (rows: lane>>2 and lane>>2 + 8)
        #pragma unroll
        for (int nt = 0; nt < 4; nt++) {
            int col = t * 32 + nt * 8 + 2 * (lane & 3);
            float v;
            v = C[nt][0];
            if (v > best0) { sec0 = best0; best0 = v; idx0 = col; }
            else if (v > sec0) sec0 = v;
            v = C[nt][1];
            if (v > best0) { sec0 = best0; best0 = v; idx0 = col + 1; }
            else if (v > sec0) sec0 = v;
            v = C[nt][2];
            if (v > best1) { sec1 = best1; best1 = v; idx1 = col; }
            else if (v > sec1) sec1 = v;
            v = C[nt][3];
            if (v > best1) { sec1 = best1; best1 = v; idx1 = col + 1; }
            else if (v > sec1) sec1 = v;
        }

        __syncthreads();
        if (t + 2 < 64) {
            const unsigned char* sH = g_cnb_hi + (size_t)(t + 2) * 16384;
            const unsigned char* sL = g_cnb_lo + (size_t)(t + 2) * 16384;
            uint32_t d = sb + 131072u + (uint32_t)(t & 1) * 32768u;
            #pragma unroll
            for (int i = 0; i < 4; i++) {
                uint32_t id = (uint32_t)(tid + i * 256) * 16u;
                CP_ASYNC16(d + id, sH + id);
                CP_ASYNC16(d + 16384u + id, sL + id);
            }
        }
        CP_COMMIT();  // commit (possibly empty) group to keep wait_group counts aligned
    }

    // ---- reduce top-2 across the quad (lanes sharing a row) ----
    #pragma unroll
    for (int off = 1; off <= 2; off <<= 1) {
        float ob = __shfl_xor_sync(0xffffffffu, best0, off);
        float os = __shfl_xor_sync(0xffffffffu, sec0, off);
        int   oi = __shfl_xor_sync(0xffffffffu, idx0, off);
        if (ob > best0 || (ob == best0 && oi < idx0)) {
            sec0 = fmaxf(best0, os); best0 = ob; idx0 = oi;
        } else sec0 = fmaxf(sec0, ob);
        ob = __shfl_xor_sync(0xffffffffu, best1, off);
        os = __shfl_xor_sync(0xffffffffu, sec1, off);
        oi = __shfl_xor_sync(0xffffffffu, idx1, off);
        if (ob > best1 || (ob == best1 && oi < idx1)) {
            sec1 = fmaxf(best1, os); best1 = ob; idx1 = oi;
        } else sec1 = fmaxf(sec1, ob);
    }

    if ((lane & 3) == 0) {
        int r0 = rowBase + warp * 16 + (lane >> 2);
        int r1 = r0 + 8;
        g_idx[r0] = idx0;
        g_idx[r1] = idx1;
        if (best0 - sec0 < TAU) {
            int p = atomicAdd(&g_flag_count, 1);
            if (p < MAXFLAG) g_flag_rows[p] = r0;
        }
        if (best1 - sec1 < TAU) {
            int p = atomicAdd(&g_flag_count, 1);
            if (p < MAXFLAG) g_flag_rows[p] = r1;
        }
    }
}

// ---------------- kernel 3: fp64 refine for near-tie rows (ILP fixed) ------
__global__ void k_refine(const float* __restrict__ x) {
    __shared__ float xs[DIM];
    __shared__ double sv[256];
    __shared__ int si[256];
    int t = threadIdx.x;
    int nf = g_flag_count;
    if (nf > MAXFLAG) nf = MAXFLAG;
    for (int f = blockIdx.x; f < nf; f += gridDim.x) {
        int row = g_flag_rows[f];
        xs[t] = x[(size_t)row * DIM + t];
        __syncthreads();
        double bb = -1e300; int bi = 0;
        for (int c = t; c < CB; c += 256) {
            const float* cr = g_cn + (size_t)c * DIM;
            double s0 = 0.0, s1 = 0.0, s2 = 0.0, s3 = 0.0;
            #pragma unroll 8
            for (int d = 0; d < DIM; d += 4) {
                s0 = fma((double)xs[d + 0], (double)__ldg(cr + d + 0), s0);
                s1 = fma((double)xs[d + 1], (double)__ldg(cr + d + 1), s1);
                s2 = fma((double)xs[d + 2], (double)__ldg(cr + d + 2), s2);
                s3 = fma((double)xs[d + 3], (double)__ldg(cr + d + 3), s3);
            }
            double s = (s0 + s1) + (s2 + s3);
            if (s > bb) { bb = s; bi = c; }
        }
        sv[t] = bb; si[t] = bi;
        __syncthreads();
        for (int srt = 128; srt; srt >>= 1) {
            if (t < srt) {
                if (sv[t + srt] > sv[t] ||
                    (sv[t + srt] == sv[t] && si[t + srt] < si[t])) {
                    sv[t] = sv[t + srt]; si[t] = si[t + srt];
                }
            }
            __syncthreads();
        }
        if (t == 0) g_idx[row] = si[0];
        __syncthreads();
    }
}

// ---------------- kernel 4: gather quantized + scatter sums ----------------
__global__ void k_assign(const float* __restrict__ x,
                         const float* __restrict__ embed,
                         float* __restrict__ out) {
    int warp = threadIdx.x >> 5, lane = threadIdx.x & 31;
    int row = blockIdx.x * 8 + warp;
    int idx = g_idx[row];
    const float4* e4 = (const float4*)(embed + (size_t)idx * DIM);
    const float4* xv4 = (const float4*)(x + (size_t)row * DIM);
    float4* q4 = (float4*)(out + OUT_Q + (size_t)row * DIM);
    float* es = g_embed_sum + (size_t)idx * DIM;
    #pragma unroll
    for (int h = 0; h < 2; h++) {
        int d4 = lane + h * 32;
        q4[d4] = e4[d4];
        float4 xv = xv4[d4];
        atomicAdd(es + d4 * 4 + 0, xv.x);
        atomicAdd(es + d4 * 4 + 1, xv.y);
        atomicAdd(es + d4 * 4 + 2, xv.z);
        atomicAdd(es + d4 * 4 + 3, xv.w);
    }
    if (lane == 0) {
        atomicAdd(&g_counts[idx], 1.0f);
        out[OUT_IDX + row] = (float)idx;
    }
}

// ---------------- kernel 5: EMA cluster size + laplace smoothing -----------
__global__ void k_cs(const float* __restrict__ cluster_size,
                     float* __restrict__ out) {
    int t = threadIdx.x;  // 1024 threads
    __shared__ float red[32];
    __shared__ float s_tot;
    float local = 0.f;
    float ncs[2];
    #pragma unroll
    for (int h = 0; h < 2; h++) {
        int c = t + h * 1024;
        ncs[h] = cluster_size[c] * DECAY + g_counts[c] * ONE_MINUS;
        out[OUT_CS + c] = ncs[h];
        local += ncs[h];
    }
    #pragma unroll
    for (int o = 16; o; o >>= 1) local += __shfl_xor_sync(0xffffffffu, local, o);
    if ((t & 31) == 0) red[t >> 5] = local;
    __syncthreads();
    if (t < 32) {
        float q = red[t];
        #pragma unroll
        for (int o = 16; o; o >>= 1) q += __shfl_xor_sync(0xffffffffu, q, o);
        if (t == 0) s_tot = q;
    }
    __syncthreads();
    float total = s_tot;
    float denom = total + CB * EPS;
    #pragma unroll
    for (int h = 0; h < 2; h++) {
        int c = t + h * 1024;
        g_cs_smooth[c] = (ncs[h] + EPS) / denom * total;
    }
}

// ---------------- kernel 6: EMA embed_avg + row normalize ------------------
__global__ void k_embed(const float* __restrict__ embed_avg,
                        float* __restrict__ out) {
    int c = blockIdx.x, t = threadIdx.x;
    float ea = embed_avg[c * DIM + t] * DECAY + g_embed_sum[c * DIM + t] * ONE_MINUS;
    out[OUT_EAVG + c * DIM + t] = ea;
    float v = ea / g_cs_smooth[c];
    float s = v * v;
    #pragma unroll
    for (int o = 16; o; o >>= 1) s += __shfl_xor_sync(0xffffffffu, s, o);
    __shared__ float red[8];
    if ((t & 31) == 0) red[t >> 5] = s;
    __syncthreads();
    if (t < 32) {
        float q = (t < 8) ? red[t] : 0.f;
        #pragma unroll
        for (int o = 4; o; o >>= 1) q += __shfl_xor_sync(0xffffffffu, q, o);
        if (t == 0) red[0] = q;
    }
    __syncthreads();
    float n = fmaxf(sqrtf(red[0]), 1e-12f);
    out[OUT_EMB + c * DIM + t] = v / n;
}

// ---------------- launch ---------------------------------------------------
extern "C" void kernel_launch(void* const* d_in, const int* in_sizes, int n_in,
                              void* d_out, int out_size) {
    const float* x            = (const float*)d_in[0];
    const float* embed        = (const float*)d_in[1];
    const float* cluster_size = (const float*)d_in[2];
    const float* embed_avg    = (const float*)d_in[3];
    float* out = (float*)d_out;

    (void)in_sizes; (void)n_in; (void)out_size;

    const int MMA_SMEM = 196608;  // 128KB A (hi+lo) + 2x32KB B buffers
    cudaFuncSetAttribute(k_mma, cudaFuncAttributeMaxDynamicSharedMemorySize, MMA_SMEM);

    k_setup<<<CB, DIM>>>(embed);
    k_mma<<<N_TOK / 128, 256, MMA_SMEM>>>(x);
    k_refine<<<512, 256>>>(x);
    k_assign<<<N_TOK / 8, 256>>>(x, embed, out);
    k_cs<<<1, 1024>>>(cluster_size, out);
    k_embed<<<CB, DIM>>>(embed_avg, out);
}

// round 9
// speedup vs baseline: 2.3905x; 2.0899x over previous
#include <cuda_runtime.h>
#include <cuda_bf16.h>
#include <math.h>
#include <cstdint>

#define N_TOK 65536
#define DIM 256
#define CB 2048
#define DECAY 0.99f
#define ONE_MINUS 0.01f
#define EPS 1e-5f

// output layout (float32 elements, reference return order)
#define OUT_Q    0u
#define OUT_IDX  16777216u
#define OUT_EMB  16842752u
#define OUT_CS   17367040u
#define OUT_EAVG 17369088u

#define TAU 1e-4f        // ~25 sigma of 3-pass bf16 margin error
#define MAXFLAG 16384

// ---------------- scratch (device globals; no allocations) ----------------
__device__ float g_cn[CB * DIM];                               // normalized codebook fp32 (refine)
__device__ __align__(128) unsigned char g_cnb_hi[CB * DIM * 2];// bf16 hi, tile-swizzled
__device__ __align__(128) unsigned char g_cnb_lo[CB * DIM * 2];// bf16 lo, tile-swizzled
__device__ float g_counts[CB];
__device__ float g_embed_sum[CB * DIM];
__device__ float g_cs_smooth[CB];
__device__ int   g_idx[N_TOK];
__device__ int   g_flag_rows[MAXFLAG];
__device__ int   g_flag_count;

// ================= PTX helpers =============================================
__device__ __forceinline__ uint32_t smem_u32(const void* p) {
    uint32_t a;
    asm("{ .reg .u64 t; cvta.to.shared.u64 t, %1; cvt.u32.u64 %0, t; }" : "=r"(a) : "l"(p));
    return a;
}

#define CP_ASYNC16(dst, src) \
    asm volatile("cp.async.cg.shared.global [%0], [%1], 16;" :: "r"(dst), "l"(src) : "memory")
#define CP_COMMIT() asm volatile("cp.async.commit_group;" ::: "memory")
#define CP_WAIT1()  asm volatile("cp.async.wait_group 1;" ::: "memory")

#define LDSM_X4(r0, r1, r2, r3, addr) \
    asm volatile("ldmatrix.sync.aligned.m8n8.x4.shared.b16 {%0,%1,%2,%3}, [%4];" \
        : "=r"(r0), "=r"(r1), "=r"(r2), "=r"(r3) : "r"(addr))

#define MMA16816(d, a0, a1, a2, a3, b0, b1) \
    asm volatile("mma.sync.aligned.m16n8k16.row.col.f32.bf16.bf16.f32 " \
        "{%0,%1,%2,%3}, {%4,%5,%6,%7}, {%8,%9}, {%0,%1,%2,%3};" \
        : "+f"((d)[0]), "+f"((d)[1]), "+f"((d)[2]), "+f"((d)[3]) \
        : "r"(a0), "r"(a1), "r"(a2), "r"(a3), "r"(b0), "r"(b1))

// ---------------- kernel 1: normalize codes + bf16 hi/lo + zero accum -----
__global__ void k_setup(const float* __restrict__ embed) {
    int c = blockIdx.x, t = threadIdx.x;
    float v = embed[c * DIM + t];
    float s = v * v;
    #pragma unroll
    for (int o = 16; o; o >>= 1) s += __shfl_xor_sync(0xffffffffu, s, o);
    __shared__ float red[8];
    if ((t & 31) == 0) red[t >> 5] = s;
    __syncthreads();
    if (t < 32) {
        float q = (t < 8) ? red[t] : 0.f;
        #pragma unroll
        for (int o = 4; o; o >>= 1) q += __shfl_xor_sync(0xffffffffu, q, o);
        if (t == 0) red[0] = q;
    }
    __syncthreads();
    float n = fmaxf(sqrtf(red[0]), 1e-12f);
    float cn = v / n;
    g_cn[c * DIM + t] = cn;

    // bf16 hi/lo into 32-code tile layout with XOR16 swizzle
    __nv_bfloat16 hb = __float2bfloat16(cn);
    float hf = __bfloat162float(hb);
    __nv_bfloat16 lb = __float2bfloat16(cn - hf);
    int tile = c >> 5;
    int r = c & 31;
    int k = t;
    uint32_t off = (uint32_t)tile * 16384u + (uint32_t)r * 512u
                 + (uint32_t)((((k >> 3) ^ (r & 7)) << 4) + (k & 7) * 2);
    *(__nv_bfloat16*)(g_cnb_hi + off) = hb;
    *(__nv_bfloat16*)(g_cnb_lo + off) = lb;

    g_embed_sum[c * DIM + t] = 0.f;
    if (t == 0) {
        g_counts[c] = 0.f;
        if (c == 0) g_flag_count = 0;
    }
}

// ---------------- kernel 2: bf16x3 HMMA GEMM + fused per-row top-2 ---------
// 256 threads = 8 warps; warp w owns rows [w*16, w*16+16).
// smem: A_hi [0,64K), A_lo [64K,128K), B double buffer [128K,192K)
__global__ void __launch_bounds__(256, 1)
k_mma(const float* __restrict__ x) {
    extern __shared__ __align__(128) unsigned char sm[];
    uint32_t sb = smem_u32(sm);
    int tid = threadIdx.x;
    int warp = tid >> 5, lane = tid & 31;
    int rowBase = blockIdx.x * 128;

    // ---- prefetch first two B tiles ----
    {
        const unsigned char* sH = g_cnb_hi;
        const unsigned char* sL = g_cnb_lo;
        uint32_t d0 = sb + 131072u;
        #pragma unroll
        for (int i = 0; i < 4; i++) {
            uint32_t id = (uint32_t)(tid + i * 256) * 16u;
            CP_ASYNC16(d0 + id, sH + id);
            CP_ASYNC16(d0 + 16384u + id, sL + id);
        }
        CP_COMMIT();
        uint32_t d1 = sb + 131072u + 32768u;
        #pragma unroll
        for (int i = 0; i < 4; i++) {
            uint32_t id = (uint32_t)(tid + i * 256) * 16u;
            CP_ASYNC16(d1 + id, sH + 16384u + id);
            CP_ASYNC16(d1 + 16384u + id, sL + 16384u + id);
        }
        CP_COMMIT();
    }

    // ---- stage A: x -> bf16 hi/lo swizzled smem ----
    {
        const float4* x4 = (const float4*)x + (size_t)rowBase * 64;
        #pragma unroll
        for (int i = 0; i < 32; i++) {
            int p = tid + i * 256;          // 0..8191
            int r = p >> 6, kq = p & 63;
            int k = kq * 4;
            float4 v = x4[(size_t)r * 64 + kq];
            __nv_bfloat162 h0 = __floats2bfloat162_rn(v.x, v.y);
            __nv_bfloat162 h1 = __floats2bfloat162_rn(v.z, v.w);
            float2 f0 = __bfloat1622float2(h0);
            float2 f1 = __bfloat1622float2(h1);
            __nv_bfloat162 l0 = __floats2bfloat162_rn(v.x - f0.x, v.y - f0.y);
            __nv_bfloat162 l1 = __floats2bfloat162_rn(v.z - f1.x, v.w - f1.y);
            uint32_t off = (uint32_t)r * 512u
                         + (uint32_t)((((k >> 3) ^ (r & 7)) << 4) + (k & 7) * 2);
            *(uint32_t*)(sm + off)           = *(uint32_t*)&h0;
            *(uint32_t*)(sm + off + 4)       = *(uint32_t*)&h1;
            *(uint32_t*)(sm + 65536u + off)     = *(uint32_t*)&l0;
            *(uint32_t*)(sm + 65536u + off + 4) = *(uint32_t*)&l1;
        }
    }
    __syncthreads();

    // ---- per-lane ldmatrix address components ----
    int q = lane >> 3, ja = lane & 7;
    int arow = warp * 16 + ((q & 1) << 3) + ja;
    uint32_t aRowOff = (uint32_t)arow * 512u;
    int aSw = arow & 7;
    int aKadd = q >> 1;
    int browL = ((q >> 1) << 3) + ja;
    int bKadd = q & 1;
    uint32_t bOffL0 = (uint32_t)browL * 512u;
    uint32_t bOffL1 = (uint32_t)(16 + browL) * 512u;
    int bSw0 = browL & 7;
    int bSw1 = (16 + browL) & 7;

    float best0 = -1e30f, sec0 = -1e30f, best1 = -1e30f, sec1 = -1e30f;
    int idx0 = 0, idx1 = 0;

    for (int t = 0; t < 64; t++) {
        CP_WAIT1();
        __syncthreads();

        uint32_t bHiB = sb + 131072u + (uint32_t)(t & 1) * 32768u;
        uint32_t bLoB = bHiB + 16384u;

        float C[4][4];
        #pragma unroll
        for (int nt = 0; nt < 4; nt++)
            #pragma unroll
            for (int j = 0; j < 4; j++) C[nt][j] = 0.f;

        #pragma unroll
        for (int ks = 0; ks < 16; ks++) {
            int c0 = ks * 2;
            uint32_t aOff = aRowOff + (uint32_t)(((c0 + aKadd) ^ aSw) << 4);
            uint32_t ah0, ah1, ah2, ah3, al0, al1, al2, al3;
            LDSM_X4(ah0, ah1, ah2, ah3, sb + aOff);
            LDSM_X4(al0, al1, al2, al3, sb + 65536u + aOff);

            uint32_t bO0 = bOffL0 + (uint32_t)(((c0 + bKadd) ^ bSw0) << 4);
            uint32_t bO1 = bOffL1 + (uint32_t)(((c0 + bKadd) ^ bSw1) << 4);

            uint32_t bh0, bh1, bh2, bh3, bl0, bl1, bl2, bl3;
            LDSM_X4(bh0, bh1, bh2, bh3, bHiB + bO0);
            LDSM_X4(bl0, bl1, bl2, bl3, bLoB + bO0);
            MMA16816(C[0], ah0, ah1, ah2, ah3, bh0, bh1);
            MMA16816(C[1], ah0, ah1, ah2, ah3, bh2, bh3);
            MMA16816(C[0], al0, al1, al2, al3, bh0, bh1);
            MMA16816(C[1], al0, al1, al2, al3, bh2, bh3);
            MMA16816(C[0], ah0, ah1, ah2, ah3, bl0, bl1);
            MMA16816(C[1], ah0, ah1, ah2, ah3, bl2, bl3);

            LDSM_X4(bh0, bh1, bh2, bh3, bHiB + bO1);
            LDSM_X4(bl0, bl1, bl2, bl3, bLoB + bO1);
            MMA16816(C[2], ah0, ah1, ah2, ah3, bh0, bh1);
            MMA16816(C[3], ah0, ah1, ah2, ah3, bh2, bh3);
            MMA16816(C[2], al0, al1, al2, al3, bh0, bh1);
            MMA16816(C[3], al0, al1, al2, al3, bh2, bh3);
            MMA16816(C[2], ah0, ah1, ah2, ah3, bl0, bl1);
            MMA16816(C[3], ah0, ah1, ah2, ah3, bl2, bl3);
        }

        // fold C into per-lane top-2 (rows: lane>>2 and lane>>2 + 8)
        #pragma unroll
        for (int nt = 0; nt < 4; nt++) {
            int col = t * 32 + nt * 8 + 2 * (lane & 3);
            float v;
            v = C[nt][0];
            if (v > best0) { sec0 = best0; best0 = v; idx0 = col; }
            else if (v > sec0) sec0 = v;
            v = C[nt][1];
            if (v > best0) { sec0 = best0; best0 = v; idx0 = col + 1; }
            else if (v > sec0) sec0 = v;
            v = C[nt][2];
            if (v > best1) { sec1 = best1; best1 = v; idx1 = col; }
            else if (v > sec1) sec1 = v;
            v = C[nt][3];
            if (v > best1) { sec1 = best1; best1 = v; idx1 = col + 1; }
            else if (v > sec1) sec1 = v;
        }

        __syncthreads();
        if (t + 2 < 64) {
            const unsigned char* sH = g_cnb_hi + (size_t)(t + 2) * 16384;
            const unsigned char* sL = g_cnb_lo + (size_t)(t + 2) * 16384;
            uint32_t d = sb + 131072u + (uint32_t)(t & 1) * 32768u;
            #pragma unroll
            for (int i = 0; i < 4; i++) {
                uint32_t id = (uint32_t)(tid + i * 256) * 16u;
                CP_ASYNC16(d + id, sH + id);
                CP_ASYNC16(d + 16384u + id, sL + id);
            }
        }
        CP_COMMIT();
    }

    // ---- reduce top-2 across the quad (lanes sharing a row) ----
    #pragma unroll
    for (int off = 1; off <= 2; off <<= 1) {
        float ob = __shfl_xor_sync(0xffffffffu, best0, off);
        float os = __shfl_xor_sync(0xffffffffu, sec0, off);
        int   oi = __shfl_xor_sync(0xffffffffu, idx0, off);
        if (ob > best0 || (ob == best0 && oi < idx0)) {
            sec0 = fmaxf(best0, os); best0 = ob; idx0 = oi;
        } else sec0 = fmaxf(sec0, ob);
        ob = __shfl_xor_sync(0xffffffffu, best1, off);
        os = __shfl_xor_sync(0xffffffffu, sec1, off);
        oi = __shfl_xor_sync(0xffffffffu, idx1, off);
        if (ob > best1 || (ob == best1 && oi < idx1)) {
            sec1 = fmaxf(best1, os); best1 = ob; idx1 = oi;
        } else sec1 = fmaxf(sec1, ob);
    }

    if ((lane & 3) == 0) {
        int r0 = rowBase + warp * 16 + (lane >> 2);
        int r1 = r0 + 8;
        g_idx[r0] = idx0;
        g_idx[r1] = idx1;
        if (best0 - sec0 < TAU) {
            int p = atomicAdd(&g_flag_count, 1);
            if (p < MAXFLAG) g_flag_rows[p] = r0;
        }
        if (best1 - sec1 < TAU) {
            int p = atomicAdd(&g_flag_count, 1);
            if (p < MAXFLAG) g_flag_rows[p] = r1;
        }
    }
}

// ---------------- kernel 3: fp64 refine, warp-per-code (coalesced) ---------
// One block per flagged row. Warp w scans codes w, w+8, ...; per code each
// lane loads 8 contiguous floats of the code row (coalesced LDG.128 x2),
// 8 DFMA, then xor-shuffle sum. Block-reduce over 8 warps with index tiebreak.
__global__ void k_refine(const float* __restrict__ x) {
    __shared__ float xs[DIM];
    __shared__ double wv[8];
    __shared__ int    wi[8];
    int t = threadIdx.x, warp = t >> 5, lane = t & 31;
    int nf = g_flag_count;
    if (nf > MAXFLAG) nf = MAXFLAG;
    for (int f = blockIdx.x; f < nf; f += gridDim.x) {
        int row = g_flag_rows[f];
        xs[t] = x[(size_t)row * DIM + t];
        __syncthreads();
        double xr[8];
        #pragma unroll
        for (int j = 0; j < 8; j++) xr[j] = (double)xs[lane * 8 + j];

        double bb = -1e300; int bi = 0;
        #pragma unroll 4
        for (int c = warp; c < CB; c += 8) {
            const float4* cr = (const float4*)(g_cn + (size_t)c * DIM);
            float4 a = cr[lane * 2];
            float4 b = cr[lane * 2 + 1];
            double s =      xr[0] * (double)a.x;
            s = fma(xr[1], (double)a.y, s);
            s = fma(xr[2], (double)a.z, s);
            s = fma(xr[3], (double)a.w, s);
            s = fma(xr[4], (double)b.x, s);
            s = fma(xr[5], (double)b.y, s);
            s = fma(xr[6], (double)b.z, s);
            s = fma(xr[7], (double)b.w, s);
            #pragma unroll
            for (int o = 16; o; o >>= 1) s += __shfl_xor_sync(0xffffffffu, s, o);
            if (s > bb) { bb = s; bi = c; }   // c ascending -> first-max kept
        }
        if (lane == 0) { wv[warp] = bb; wi[warp] = bi; }
        __syncthreads();
        if (t == 0) {
            double B = wv[0]; int I = wi[0];
            #pragma unroll
            for (int w = 1; w < 8; w++) {
                if (wv[w] > B || (wv[w] == B && wi[w] < I)) { B = wv[w]; I = wi[w]; }
            }
            g_idx[row] = I;
        }
        __syncthreads();
    }
}

// ---------------- kernel 4: gather quantized + scatter sums ----------------
__global__ void k_assign(const float* __restrict__ x,
                         const float* __restrict__ embed,
                         float* __restrict__ out) {
    int warp = threadIdx.x >> 5, lane = threadIdx.x & 31;
    int row = blockIdx.x * 8 + warp;
    int idx = g_idx[row];
    const float4* e4 = (const float4*)(embed + (size_t)idx * DIM);
    const float4* xv4 = (const float4*)(x + (size_t)row * DIM);
    float4* q4 = (float4*)(out + OUT_Q + (size_t)row * DIM);
    float* es = g_embed_sum + (size_t)idx * DIM;
    #pragma unroll
    for (int h = 0; h < 2; h++) {
        int d4 = lane + h * 32;
        q4[d4] = e4[d4];
        float4 xv = xv4[d4];
        atomicAdd(es + d4 * 4 + 0, xv.x);
        atomicAdd(es + d4 * 4 + 1, xv.y);
        atomicAdd(es + d4 * 4 + 2, xv.z);
        atomicAdd(es + d4 * 4 + 3, xv.w);
    }
    if (lane == 0) {
        atomicAdd(&g_counts[idx], 1.0f);
        out[OUT_IDX + row] = (float)idx;
    }
}

// ---------------- kernel 5: EMA cluster size + laplace smoothing -----------
__global__ void k_cs(const float* __restrict__ cluster_size,
                     float* __restrict__ out) {
    int t = threadIdx.x;  // 1024 threads
    __shared__ float red[32];
    __shared__ float s_tot;
    float local = 0.f;
    float ncs[2];
    #pragma unroll
    for (int h = 0; h < 2; h++) {
        int c = t + h * 1024;
        ncs[h] = cluster_size[c] * DECAY + g_counts[c] * ONE_MINUS;
        out[OUT_CS + c] = ncs[h];
        local += ncs[h];
    }
    #pragma unroll
    for (int o = 16; o; o >>= 1) local += __shfl_xor_sync(0xffffffffu, local, o);
    if ((t & 31) == 0) red[t >> 5] = local;
    __syncthreads();
    if (t < 32) {
        float q = red[t];
        #pragma unroll
        for (int o = 16; o; o >>= 1) q += __shfl_xor_sync(0xffffffffu, q, o);
        if (t == 0) s_tot = q;
    }
    __syncthreads();
    float total = s_tot;
    float denom = total + CB * EPS;
    #pragma unroll
    for (int h = 0; h < 2; h++) {
        int c = t + h * 1024;
        g_cs_smooth[c] = (ncs[h] + EPS) / denom * total;
    }
}

// ---------------- kernel 6: EMA embed_avg + row normalize ------------------
__global__ void k_embed(const float* __restrict__ embed_avg,
                        float* __restrict__ out) {
    int c = blockIdx.x, t = threadIdx.x;
    float ea = embed_avg[c * DIM + t] * DECAY + g_embed_sum[c * DIM + t] * ONE_MINUS;
    out[OUT_EAVG + c * DIM + t] = ea;
    float v = ea / g_cs_smooth[c];
    float s = v * v;
    #pragma unroll
    for (int o = 16; o; o >>= 1) s += __shfl_xor_sync(0xffffffffu, s, o);
    __shared__ float red[8];
    if ((t & 31) == 0) red[t >> 5] = s;
    __syncthreads();
    if (t < 32) {
        float q = (t < 8) ? red[t] : 0.f;
        #pragma unroll
        for (int o = 4; o; o >>= 1) q += __shfl_xor_sync(0xffffffffu, q, o);
        if (t == 0) red[0] = q;
    }
    __syncthreads();
    float n = fmaxf(sqrtf(red[0]), 1e-12f);
    out[OUT_EMB + c * DIM + t] = v / n;
}

// ---------------- launch ---------------------------------------------------
extern "C" void kernel_launch(void* const* d_in, const int* in_sizes, int n_in,
                              void* d_out, int out_size) {
    const float* x            = (const float*)d_in[0];
    const float* embed        = (const float*)d_in[1];
    const float* cluster_size = (const float*)d_in[2];
    const float* embed_avg    = (const float*)d_in[3];
    float* out = (float*)d_out;

    (void)in_sizes; (void)n_in; (void)out_size;

    const int MMA_SMEM = 196608;  // 128KB A (hi+lo) + 2x32KB B buffers
    cudaFuncSetAttribute(k_mma, cudaFuncAttributeMaxDynamicSharedMemorySize, MMA_SMEM);

    k_setup<<<CB, DIM>>>(embed);
    k_mma<<<N_TOK / 128, 256, MMA_SMEM>>>(x);
    k_refine<<<128, 256>>>(x);
    k_assign<<<N_TOK / 8, 256>>>(x, embed, out);
    k_cs<<<1, 1024>>>(cluster_size, out);
    k_embed<<<CB, DIM>>>(embed_avg, out);
}